// round 14
// baseline (speedup 1.0000x reference)
#include <cuda_runtime.h>
#include <cstdint>

// Problem shape (fixed by the dataset)
#define NROWS 200000
#define NNZV  2000000
#define DIN   300
#define DOUT  96
#define CAP   64   // 512B-aligned bin rows; Poisson(10), overflow ~1e-30

// Scratch: allocation-free (__device__ globals; zero-initialized at module load)
__device__ int g_cnt[NROWS];
__device__ unsigned long long g_bins[(size_t)NROWS * CAP];

// 4 nonzeros per thread: vectorized index/value loads, 4x atomic MLP.
__global__ void __launch_bounds__(256) scatter_kernel(
        const float4* __restrict__ val4,
        const int4*   __restrict__ row4,
        const int4*   __restrict__ col4) {
    int k = blockIdx.x * blockDim.x + threadIdx.x;
    if (k >= NNZV / 4) return;
    int4   r = row4[k];
    int4   c = col4[k];
    float4 v = val4[k];

    int p0 = atomicAdd(&g_cnt[r.x], 1);
    int p1 = atomicAdd(&g_cnt[r.y], 1);
    int p2 = atomicAdd(&g_cnt[r.z], 1);
    int p3 = atomicAdd(&g_cnt[r.w], 1);

    if (p0 < CAP) g_bins[(size_t)r.x * CAP + p0] =
        ((unsigned long long)(unsigned)c.x << 32) | __float_as_uint(v.x);
    if (p1 < CAP) g_bins[(size_t)r.y * CAP + p1] =
        ((unsigned long long)(unsigned)c.y << 32) | __float_as_uint(v.y);
    if (p2 < CAP) g_bins[(size_t)r.z * CAP + p2] =
        ((unsigned long long)(unsigned)c.z << 32) | __float_as_uint(v.z);
    if (p3 < CAP) g_bins[(size_t)r.w * CAP + p3] =
        ((unsigned long long)(unsigned)c.w << 32) | __float_as_uint(v.w);
}

// Warp-per-row. Inner loop processes 4 entries per iteration, branch-free:
// padded entries are ZERO (lane >= n holds mine = 0, so shfl gives v=0,c=0
// -> reads W[0..96) and adds exactly 0). 12 independent LDGs in flight per
// iteration (MLP 12) instead of 3 — attacks the measured latency bound
// (issue 36%, all pipes < 40% in round 11).
__global__ void __launch_bounds__(256) compute_kernel(
        const float* __restrict__ W,     // [300, 96]
        const float* __restrict__ b,     // [96]
        const float* __restrict__ mask,  // [NROWS]
        float* __restrict__ out) {       // [NROWS, 96]
    int warp = (blockIdx.x * blockDim.x + threadIdx.x) >> 5;
    int lane = threadIdx.x & 31;
    if (warp >= NROWS) return;
    int row = warp;

    int cnt = g_cnt[row];
    if (lane == 0) g_cnt[row] = 0;          // reset for next graph replay
    if (cnt > CAP) cnt = CAP;
    const unsigned long long* __restrict__ bins = g_bins + (size_t)row * CAP;

    float a0 = 0.f, a1 = 0.f, a2 = 0.f;
    for (int base = 0; base < cnt; base += 32) {
        int n = cnt - base;
        if (n > 32) n = 32;
        // Coalesced load; lanes >= n hold 0 (zero-padding for the 4x body).
        unsigned long long mine = (lane < n) ? bins[base + lane] : 0ull;
        int n4 = (n + 3) & ~3;
        for (int i = 0; i < n4; i += 4) {
            unsigned long long e0 = __shfl_sync(0xffffffffu, mine, i);
            unsigned long long e1 = __shfl_sync(0xffffffffu, mine, i + 1);
            unsigned long long e2 = __shfl_sync(0xffffffffu, mine, i + 2);
            unsigned long long e3 = __shfl_sync(0xffffffffu, mine, i + 3);

            float v0 = __uint_as_float((unsigned)e0);
            float v1 = __uint_as_float((unsigned)e1);
            float v2 = __uint_as_float((unsigned)e2);
            float v3 = __uint_as_float((unsigned)e3);
            const float* w0 = W + (int)(e0 >> 32) * DOUT;
            const float* w1 = W + (int)(e1 >> 32) * DOUT;
            const float* w2 = W + (int)(e2 >> 32) * DOUT;
            const float* w3 = W + (int)(e3 >> 32) * DOUT;

            // 12 independent loads — issued before any FMA consumes them.
            float x00 = w0[lane], x01 = w0[lane + 32], x02 = w0[lane + 64];
            float x10 = w1[lane], x11 = w1[lane + 32], x12 = w1[lane + 64];
            float x20 = w2[lane], x21 = w2[lane + 32], x22 = w2[lane + 64];
            float x30 = w3[lane], x31 = w3[lane + 32], x32 = w3[lane + 64];

            a0 = fmaf(v0, x00, a0); a1 = fmaf(v0, x01, a1); a2 = fmaf(v0, x02, a2);
            a0 = fmaf(v1, x10, a0); a1 = fmaf(v1, x11, a1); a2 = fmaf(v1, x12, a2);
            a0 = fmaf(v2, x20, a0); a1 = fmaf(v2, x21, a1); a2 = fmaf(v2, x22, a2);
            a0 = fmaf(v3, x30, a0); a1 = fmaf(v3, x31, a1); a2 = fmaf(v3, x32, a2);
        }
    }

    float m = mask[row];
    float* o = out + (size_t)row * DOUT;
    o[lane]      = m * fmaxf(a0 + b[lane],      0.f);
    o[lane + 32] = m * fmaxf(a1 + b[lane + 32], 0.f);
    o[lane + 64] = m * fmaxf(a2 + b[lane + 64], 0.f);
}

extern "C" void kernel_launch(void* const* d_in, const int* in_sizes, int n_in,
                              void* d_out, int out_size) {
    // x_values f32[2M], mask f32[200K], W f32[300*96], b f32[96],
    // x_row i32[2M], x_col i32[2M]   (jax demotes int64->int32)
    const float* x_values = (const float*)d_in[0];
    const float* mask     = (const float*)d_in[1];
    const float* W        = (const float*)d_in[2];
    const float* b        = (const float*)d_in[3];
    const int*   x_row    = (const int*)d_in[4];
    const int*   x_col    = (const int*)d_in[5];
    float* out = (float*)d_out;
    (void)in_sizes; (void)n_in; (void)out_size;

    scatter_kernel<<<(NNZV / 4 + 255) / 256, 256>>>(
        (const float4*)x_values, (const int4*)x_row, (const int4*)x_col);
    // 200K warps, 8 warps per 256-thread block
    compute_kernel<<<(NROWS + 7) / 8, 256>>>(W, b, mask, out);
}